// round 1
// baseline (speedup 1.0000x reference)
#include <cuda_runtime.h>
#include <cuda_bf16.h>
#include <cstdint>

// ---------------------------------------------------------------------------
// BotRGCN fused pipeline for GB300.
// Sizes fixed by the problem: N=100000 nodes, E=3200000 edges, D=128, R=2.
//
// Restructuring:
//   rgcn(x) = x@W_root + b + sum_r mean_r(x) @ W_rel[r]
//           = [x | mean_0(x) | mean_1(x)] @ [W_root; W_rel0; W_rel1] + b
// One [N,384]@[384,128] GEMM per layer. mean_r computed via CSR gather
// (edge list bucketed by segment = dst*2 + edge_type, built once per launch).
// ---------------------------------------------------------------------------

#define MAXN 100000
#define MAXE 3200000
#define NRSEG (MAXN * 2)

__device__ __align__(256) float g_A[(size_t)MAXN * 384];
__device__ __align__(256) float g_B[(size_t)MAXN * 384];
__device__ __align__(256) float g_Wcat[384 * 128];
__device__ __align__(256) int   g_perm[MAXE];
__device__ __align__(256) int   g_rowptr[NRSEG + 1];
__device__ __align__(256) int   g_cnt[NRSEG];
__device__ __align__(256) int   g_cursor[NRSEG];
__device__ __align__(256) int   g_scan[NRSEG];
__device__ __align__(256) int   g_bsums[512];

// ------------------------- CSR build --------------------------------------

__global__ void count_kernel(const int* __restrict__ dst,
                             const int* __restrict__ et, int E,
                             int* __restrict__ cnt) {
    int i = blockIdx.x * blockDim.x + threadIdx.x;
    if (i < E) atomicAdd(&cnt[dst[i] * 2 + et[i]], 1);
}

__global__ void scan_block_kernel(const int* __restrict__ cnt,
                                  int* __restrict__ scanout,
                                  int* __restrict__ bsums, int n) {
    __shared__ int s[1024];
    int idx = blockIdx.x * 1024 + threadIdx.x;
    int v = (idx < n) ? cnt[idx] : 0;
    s[threadIdx.x] = v;
    __syncthreads();
    // Hillis-Steele inclusive scan
    for (int off = 1; off < 1024; off <<= 1) {
        int t = (threadIdx.x >= off) ? s[threadIdx.x - off] : 0;
        __syncthreads();
        s[threadIdx.x] += t;
        __syncthreads();
    }
    if (idx < n) scanout[idx] = s[threadIdx.x];
    if (threadIdx.x == 1023) bsums[blockIdx.x] = s[1023];
}

__global__ void scan_bsums_kernel(int* bsums, int nb) {
    if (blockIdx.x == 0 && threadIdx.x == 0) {
        int run = 0;
        for (int i = 0; i < nb; i++) {
            int v = bsums[i];
            bsums[i] = run;
            run += v;
        }
    }
}

__global__ void scan_finalize_kernel(const int* __restrict__ scanout,
                                     const int* __restrict__ bsums,
                                     int* __restrict__ rowptr, int n) {
    int idx = blockIdx.x * blockDim.x + threadIdx.x;
    if (idx == 0) rowptr[0] = 0;
    if (idx < n) rowptr[idx + 1] = scanout[idx] + bsums[idx >> 10];
}

__global__ void place_kernel(const int* __restrict__ src,
                             const int* __restrict__ dst,
                             const int* __restrict__ et, int E,
                             const int* __restrict__ rowptr,
                             int* __restrict__ cursor,
                             int* __restrict__ perm) {
    int i = blockIdx.x * blockDim.x + threadIdx.x;
    if (i < E) {
        int seg = dst[i] * 2 + et[i];
        int p = atomicAdd(&cursor[seg], 1);
        perm[rowptr[seg] + p] = src[i];
    }
}

// ------------------------- Wcat build --------------------------------------
// Wcat[384,128] = [W_root(128x128); W_rel(2x128x128 contiguous)]
__global__ void build_wcat_kernel(const float* __restrict__ W_root,
                                  const float* __restrict__ W_rel,
                                  float* __restrict__ Wcat) {
    int i = blockIdx.x * blockDim.x + threadIdx.x;
    if (i < 384 * 128) {
        int k = i >> 7;  // row
        Wcat[i] = (k < 128) ? W_root[i] : W_rel[i - 128 * 128];
    }
}

// ------------------------- GEMM + bias (+ leaky relu) ----------------------

template <int BM, int BN, int BK, int TM, int TN>
__global__ void gemm_bias_act(const float* __restrict__ A, int lda,
                              const float* __restrict__ Bm, int ldb,
                              const float* __restrict__ bias,
                              float* __restrict__ C, int ldc,
                              int M, int Ncols, int K, int act) {
    constexpr int THREADS = (BM / TM) * (BN / TN);
    __shared__ float As[BK][BM];
    __shared__ float Bs[BK][BN];
    const int tid = threadIdx.x;
    const int tcol = tid % (BN / TN);
    const int trow = tid / (BN / TN);
    const int row0 = blockIdx.y * BM;
    const int col0 = blockIdx.x * BN;

    float acc[TM][TN];
#pragma unroll
    for (int i = 0; i < TM; i++)
#pragma unroll
        for (int j = 0; j < TN; j++) acc[i][j] = 0.f;

    for (int k0 = 0; k0 < K; k0 += BK) {
#pragma unroll
        for (int i = tid; i < BM * BK; i += THREADS) {
            int r = i / BK, c = i % BK;
            int gr = row0 + r, gc = k0 + c;
            As[c][r] = (gr < M && gc < K) ? A[(size_t)gr * lda + gc] : 0.f;
        }
#pragma unroll
        for (int i = tid; i < BK * BN; i += THREADS) {
            int r = i / BN, c = i % BN;
            int gr = k0 + r, gc = col0 + c;
            Bs[r][c] = (gr < K && gc < Ncols) ? Bm[(size_t)gr * ldb + gc] : 0.f;
        }
        __syncthreads();
#pragma unroll
        for (int kk = 0; kk < BK; kk++) {
            float a[TM], b[TN];
#pragma unroll
            for (int i = 0; i < TM; i++) a[i] = As[kk][trow * TM + i];
#pragma unroll
            for (int j = 0; j < TN; j++) b[j] = Bs[kk][tcol * TN + j];
#pragma unroll
            for (int i = 0; i < TM; i++)
#pragma unroll
                for (int j = 0; j < TN; j++) acc[i][j] += a[i] * b[j];
        }
        __syncthreads();
    }

#pragma unroll
    for (int i = 0; i < TM; i++) {
        int gr = row0 + trow * TM + i;
        if (gr >= M) continue;
#pragma unroll
        for (int j = 0; j < TN; j++) {
            int gc = col0 + tcol * TN + j;
            if (gc >= Ncols) continue;
            float v = acc[i][j] + bias[gc];
            if (act) v = (v >= 0.f) ? v : 0.01f * v;
            C[(size_t)gr * ldc + gc] = v;
        }
    }
}

// ------------------------- Aggregation (CSR gather, warp/segment) ----------
// buf: [N, 384]; reads cols 0..127 (x), writes cols 128..383 (mean_r0|mean_r1)

__global__ void aggregate_kernel(float* __restrict__ buf,
                                 const int* __restrict__ rowptr,
                                 const int* __restrict__ perm, int NR) {
    int w = blockIdx.x * (blockDim.x >> 5) + (threadIdx.x >> 5);
    if (w >= NR) return;
    int lane = threadIdx.x & 31;
    int start = rowptr[w];
    int end = rowptr[w + 1];
    float4 acc = make_float4(0.f, 0.f, 0.f, 0.f);
    for (int e = start; e < end; e++) {
        int s = perm[e];
        const float4 v =
            *reinterpret_cast<const float4*>(buf + (size_t)s * 384 + lane * 4);
        acc.x += v.x; acc.y += v.y; acc.z += v.z; acc.w += v.w;
    }
    int deg = end - start;
    float inv = 1.f / (float)max(deg, 1);
    acc.x *= inv; acc.y *= inv; acc.z *= inv; acc.w *= inv;
    int node = w >> 1, r = w & 1;
    *reinterpret_cast<float4*>(buf + (size_t)node * 384 + 128 + r * 128 +
                               lane * 4) = acc;
}

// ------------------------- Output head (logits + softmax) ------------------

__global__ void head_kernel(const float* __restrict__ buf,
                            const float* __restrict__ W_o2,
                            const float* __restrict__ b_o2,
                            float* __restrict__ out, int N) {
    int w = blockIdx.x * (blockDim.x >> 5) + (threadIdx.x >> 5);
    if (w >= N) return;
    int lane = threadIdx.x & 31;
    const float4 v =
        *reinterpret_cast<const float4*>(buf + (size_t)w * 384 + lane * 4);
    int k = lane * 4;
    float d0 = v.x * W_o2[(k + 0) * 2] + v.y * W_o2[(k + 1) * 2] +
               v.z * W_o2[(k + 2) * 2] + v.w * W_o2[(k + 3) * 2];
    float d1 = v.x * W_o2[(k + 0) * 2 + 1] + v.y * W_o2[(k + 1) * 2 + 1] +
               v.z * W_o2[(k + 2) * 2 + 1] + v.w * W_o2[(k + 3) * 2 + 1];
#pragma unroll
    for (int off = 16; off; off >>= 1) {
        d0 += __shfl_xor_sync(0xFFFFFFFFu, d0, off);
        d1 += __shfl_xor_sync(0xFFFFFFFFu, d1, off);
    }
    if (lane == 0) {
        float l0 = d0 + b_o2[0], l1 = d1 + b_o2[1];
        float m = fmaxf(l0, l1);
        float e0 = __expf(l0 - m), e1 = __expf(l1 - m);
        float inv = 1.f / (e0 + e1);
        out[(size_t)w * 2] = e0 * inv;
        out[(size_t)w * 2 + 1] = e1 * inv;
    }
}

// ------------------------- Launch ------------------------------------------

extern "C" void kernel_launch(void* const* d_in, const int* in_sizes, int n_in,
                              void* d_out, int out_size) {
    const float* des     = (const float*)d_in[0];
    const float* tweet   = (const float*)d_in[1];
    const float* prop    = (const float*)d_in[2];
    const int*   eidx    = (const int*)d_in[3];
    const int*   etype   = (const int*)d_in[4];
    const float* W_des   = (const float*)d_in[5];
    const float* b_des   = (const float*)d_in[6];
    const float* W_tweet = (const float*)d_in[7];
    const float* b_tweet = (const float*)d_in[8];
    const float* W_prop  = (const float*)d_in[9];
    const float* b_prop  = (const float*)d_in[10];
    const float* W_in    = (const float*)d_in[11];
    const float* b_in    = (const float*)d_in[12];
    const float* W_rel   = (const float*)d_in[13];
    const float* W_root  = (const float*)d_in[14];
    const float* b_rgcn  = (const float*)d_in[15];
    const float* W_o1    = (const float*)d_in[16];
    const float* b_o1    = (const float*)d_in[17];
    const float* W_o2    = (const float*)d_in[18];
    const float* b_o2    = (const float*)d_in[19];

    const int N = in_sizes[0] / 768;
    const int E = in_sizes[4];
    const int NR = N * 2;
    const int* src = eidx;
    const int* dst = eidx + E;

    float* A;    cudaGetSymbolAddress((void**)&A, g_A);
    float* B;    cudaGetSymbolAddress((void**)&B, g_B);
    float* Wcat; cudaGetSymbolAddress((void**)&Wcat, g_Wcat);
    int* perm;   cudaGetSymbolAddress((void**)&perm, g_perm);
    int* rowptr; cudaGetSymbolAddress((void**)&rowptr, g_rowptr);
    int* cnt;    cudaGetSymbolAddress((void**)&cnt, g_cnt);
    int* cursor; cudaGetSymbolAddress((void**)&cursor, g_cursor);
    int* scanb;  cudaGetSymbolAddress((void**)&scanb, g_scan);
    int* bsums;  cudaGetSymbolAddress((void**)&bsums, g_bsums);

    // ---- CSR build (once per launch; shared by both RGCN layers) ----
    cudaMemsetAsync(cnt, 0, (size_t)NR * sizeof(int));
    cudaMemsetAsync(cursor, 0, (size_t)NR * sizeof(int));
    build_wcat_kernel<<<(384 * 128 + 255) / 256, 256>>>(W_root, W_rel, Wcat);
    count_kernel<<<(E + 255) / 256, 256>>>(dst, etype, E, cnt);
    int nb = (NR + 1023) / 1024;
    scan_block_kernel<<<nb, 1024>>>(cnt, scanb, bsums, NR);
    scan_bsums_kernel<<<1, 32>>>(bsums, nb);
    scan_finalize_kernel<<<(NR + 255) / 256, 256>>>(scanb, bsums, rowptr, NR);
    place_kernel<<<(E + 255) / 256, 256>>>(src, dst, etype, E, rowptr, cursor,
                                           perm);

    // ---- Encoder: d|t|p -> B[:,0:96], x -> A[:,0:128] ----
    {
        dim3 ge(1, (N + 63) / 64);
        gemm_bias_act<64, 32, 16, 4, 4><<<ge, 128>>>(
            des, 768, W_des, 32, b_des, B + 0, 384, N, 32, 768, 1);
        gemm_bias_act<64, 32, 16, 4, 4><<<ge, 128>>>(
            tweet, 768, W_tweet, 32, b_tweet, B + 32, 384, N, 32, 768, 1);
        gemm_bias_act<64, 32, 16, 4, 4><<<ge, 128>>>(
            prop, 14, W_prop, 32, b_prop, B + 64, 384, N, 32, 14, 1);
    }
    dim3 gb(1, (N + 127) / 128);
    gemm_bias_act<128, 128, 16, 8, 8><<<gb, 256>>>(B, 384, W_in, 128, b_in, A,
                                                   384, N, 128, 96, 1);

    // ---- RGCN layer 1: aggregate on A, fused GEMM -> B[:,0:128] ----
    aggregate_kernel<<<(NR + 7) / 8, 256>>>(A, rowptr, perm, NR);
    gemm_bias_act<128, 128, 16, 8, 8><<<gb, 256>>>(A, 384, Wcat, 128, b_rgcn,
                                                   B, 384, N, 128, 384, 0);

    // ---- RGCN layer 2: aggregate on B, fused GEMM -> A[:,0:128] ----
    aggregate_kernel<<<(NR + 7) / 8, 256>>>(B, rowptr, perm, NR);
    gemm_bias_act<128, 128, 16, 8, 8><<<gb, 256>>>(B, 384, Wcat, 128, b_rgcn,
                                                   A, 384, N, 128, 384, 0);

    // ---- Output head ----
    gemm_bias_act<128, 128, 16, 8, 8><<<gb, 256>>>(A, 384, W_o1, 128, b_o1, B,
                                                   384, N, 128, 128, 1);
    head_kernel<<<(N + 7) / 8, 256>>>(B, W_o2, b_o2, (float*)d_out, N);
}

// round 4
// speedup vs baseline: 5.5407x; 5.5407x over previous
#include <cuda_runtime.h>
#include <cuda_bf16.h>
#include <cstdint>

// ---------------------------------------------------------------------------
// BotRGCN on GB300 — bf16 mma.sync (m16n8k16) pipeline.
// (tcgen05 is unavailable: harness PTX stage targets compute_103 without 'a'.)
//   rgcn(x) = [x | mean_0(x) | mean_1(x)] @ [W_root; W_rel0; W_rel1] + b
// Activations in bf16 buffers, row stride 384. fp32 accumulation everywhere.
// ---------------------------------------------------------------------------

#define MAXN 100000
#define MAXE 3200000
#define NRSEG (MAXN * 2)

__device__ __align__(256) __nv_bfloat16 g_A[(size_t)MAXN * 384];
__device__ __align__(256) __nv_bfloat16 g_B[(size_t)MAXN * 384];
__device__ __align__(256) __nv_bfloat16 g_Wt_des[32 * 768];
__device__ __align__(256) __nv_bfloat16 g_Wt_tweet[32 * 768];
__device__ __align__(256) __nv_bfloat16 g_Wt_prop[32 * 64];
__device__ __align__(256) __nv_bfloat16 g_Wt_in[128 * 128];
__device__ __align__(256) __nv_bfloat16 g_Wt_cat[128 * 384];
__device__ __align__(256) __nv_bfloat16 g_Wt_o1[128 * 128];
__device__ __align__(256) int g_perm[MAXE];
__device__ __align__(256) int g_rowptr[NRSEG + 1];
__device__ __align__(256) int g_cnt[NRSEG];
__device__ __align__(256) int g_cursor[NRSEG];
__device__ __align__(256) int g_scan[NRSEG];
__device__ __align__(256) int g_bsums[512];

__device__ __forceinline__ uint32_t smem_u32(const void* p) {
    uint32_t a;
    asm("{ .reg .u64 t; cvta.to.shared.u64 t, %1; cvt.u32.u64 %0, t; }"
        : "=r"(a) : "l"(p));
    return a;
}

// ------------------------- CSR build ---------------------------------------

__global__ void count_kernel(const int* __restrict__ dst,
                             const int* __restrict__ et, int E,
                             int* __restrict__ cnt) {
    int i = blockIdx.x * blockDim.x + threadIdx.x;
    if (i < E) atomicAdd(&cnt[dst[i] * 2 + et[i]], 1);
}

__global__ void scan_block_kernel(const int* __restrict__ cnt,
                                  int* __restrict__ scanout,
                                  int* __restrict__ bsums, int n) {
    __shared__ int s[1024];
    int idx = blockIdx.x * 1024 + threadIdx.x;
    int v = (idx < n) ? cnt[idx] : 0;
    s[threadIdx.x] = v;
    __syncthreads();
    for (int off = 1; off < 1024; off <<= 1) {
        int t = (threadIdx.x >= off) ? s[threadIdx.x - off] : 0;
        __syncthreads();
        s[threadIdx.x] += t;
        __syncthreads();
    }
    if (idx < n) scanout[idx] = s[threadIdx.x];
    if (threadIdx.x == 1023) bsums[blockIdx.x] = s[1023];
}

__global__ void scan_bsums_kernel(int* bsums, int nb) {
    if (blockIdx.x == 0 && threadIdx.x == 0) {
        int run = 0;
        for (int i = 0; i < nb; i++) {
            int v = bsums[i];
            bsums[i] = run;
            run += v;
        }
    }
}

__global__ void scan_finalize_kernel(const int* __restrict__ scanout,
                                     const int* __restrict__ bsums,
                                     int* __restrict__ rowptr, int n) {
    int idx = blockIdx.x * blockDim.x + threadIdx.x;
    if (idx == 0) rowptr[0] = 0;
    if (idx < n) rowptr[idx + 1] = scanout[idx] + bsums[idx >> 10];
}

__global__ void place_kernel(const int* __restrict__ src,
                             const int* __restrict__ dst,
                             const int* __restrict__ et, int E,
                             const int* __restrict__ rowptr,
                             int* __restrict__ cursor, int* __restrict__ perm) {
    int i = blockIdx.x * blockDim.x + threadIdx.x;
    if (i < E) {
        int seg = dst[i] * 2 + et[i];
        int p = atomicAdd(&cursor[seg], 1);
        perm[rowptr[seg] + p] = src[i];
    }
}

// ------------------------- Weight prep -------------------------------------
// in: [K, Nw] fp32 row-major  ->  out: [Nw, Kpad] bf16 (zero-padded K)

__global__ void transpose_convert(const float* __restrict__ in,
                                  __nv_bfloat16* __restrict__ out, int K,
                                  int Nw, int Kpad) {
    int idx = blockIdx.x * blockDim.x + threadIdx.x;
    if (idx < Nw * Kpad) {
        int n = idx / Kpad, k = idx % Kpad;
        out[idx] = (k < K) ? __float2bfloat16_rn(in[k * Nw + n])
                           : __float2bfloat16_rn(0.f);
    }
}

__global__ void wcat_transpose(const float* __restrict__ W_root,
                               const float* __restrict__ W_rel,
                               __nv_bfloat16* __restrict__ out) {
    int idx = blockIdx.x * blockDim.x + threadIdx.x;
    if (idx < 128 * 384) {
        int n = idx / 384, k = idx % 384;
        float v = (k < 128) ? W_root[k * 128 + n] : W_rel[(k - 128) * 128 + n];
        out[idx] = __float2bfloat16_rn(v);
    }
}

// ------------------------- mma.sync GEMM -----------------------------------
// C[M, BN](bf16, stride ldc) = act( A[M,K] @ Wt[BN,K]^T + bias )
// A fp32 (AFP32) or bf16; Wt bf16, K zero-padded to ldw.
// BM=128, BK=32. BN=128: 8 warps (4x2), warp tile 32x64.
//                BN=32 : 4 warps (4x1), warp tile 32x32.

#define LDMX4(r0, r1, r2, r3, addr)                                           \
    asm volatile("ldmatrix.sync.aligned.m8n8.x4.shared.b16 {%0,%1,%2,%3}, [%4];" \
                 : "=r"(r0), "=r"(r1), "=r"(r2), "=r"(r3) : "r"(addr))
#define LDMX2(r0, r1, addr)                                                   \
    asm volatile("ldmatrix.sync.aligned.m8n8.x2.shared.b16 {%0,%1}, [%2];"    \
                 : "=r"(r0), "=r"(r1) : "r"(addr))
#define MMA16816(c, a, b)                                                     \
    asm volatile(                                                             \
        "mma.sync.aligned.m16n8k16.row.col.f32.bf16.bf16.f32 "                \
        "{%0,%1,%2,%3}, {%4,%5,%6,%7}, {%8,%9}, {%0,%1,%2,%3};"               \
        : "+f"((c)[0]), "+f"((c)[1]), "+f"((c)[2]), "+f"((c)[3])              \
        : "r"((a)[0]), "r"((a)[1]), "r"((a)[2]), "r"((a)[3]),                 \
          "r"((b)[0]), "r"((b)[1]))

template <bool AFP32, int BN>
__global__ void __launch_bounds__(BN == 128 ? 256 : 128) gemm_mma(
    const void* __restrict__ Aptr, int lda,
    const __nv_bfloat16* __restrict__ Wt, int ldw,
    const float* __restrict__ bias, __nv_bfloat16* __restrict__ C, int ldc,
    int M, int K, int act) {
    constexpr int WARPS_N = (BN == 128) ? 2 : 1;
    constexpr int THREADS = 128 * WARPS_N;
    constexpr int WN = BN / WARPS_N;   // 64 or 32
    constexpr int NATOMS = WN / 8;     // 8 or 4
    constexpr int STR = 40;            // smem row stride in bf16 elems (80B)

    __shared__ __nv_bfloat16 sA[128 * STR];
    __shared__ __nv_bfloat16 sB[BN * STR];

    const int tid = threadIdx.x;
    const int wid = tid >> 5, lane = tid & 31;
    const int wm = wid & 3, wn = wid >> 2;
    const int row0 = blockIdx.x * 128;
    const uint32_t baseA = smem_u32(sA);
    const uint32_t baseB = smem_u32(sB);

    float acc[2][NATOMS][4];
#pragma unroll
    for (int i = 0; i < 2; i++)
#pragma unroll
        for (int j = 0; j < NATOMS; j++)
#pragma unroll
            for (int q = 0; q < 4; q++) acc[i][j][q] = 0.f;

    // precomputed ldmatrix lane addresses (chunk-invariant; k-step adds 32B)
    uint32_t aAddr[2];
#pragma unroll
    for (int i = 0; i < 2; i++)
        aAddr[i] = baseA + (uint32_t)(((wm * 32 + i * 16 + (lane & 15)) * STR +
                                       ((lane >> 4) * 8)) * 2);
    uint32_t bAddr[NATOMS];
#pragma unroll
    for (int j = 0; j < NATOMS; j++)
        bAddr[j] = baseB + (uint32_t)(((wn * WN + j * 8 + (lane & 7)) * STR +
                                       (((lane >> 3) & 1) * 8)) * 2);

    const int nchunks = (K + 31) >> 5;
    for (int c = 0; c < nchunks; c++) {
        const int k0 = c << 5;
        // ---- global -> smem (8 elems per iteration) ----
#pragma unroll 2
        for (int idx = tid; idx < 128 * 4; idx += THREADS) {
            int r = idx >> 2, g = idx & 3;
            int gr = row0 + r, gc0 = k0 + g * 8;
            uint4 val;
            if (AFP32) {
                const float* Af = (const float*)Aptr;
                if (gr < M && gc0 + 7 < K && (lda & 3) == 0) {
                    const float4* p = (const float4*)(Af + (size_t)gr * lda + gc0);
                    float4 v0 = p[0], v1 = p[1];
                    __nv_bfloat162 h0 = __floats2bfloat162_rn(v0.x, v0.y);
                    __nv_bfloat162 h1 = __floats2bfloat162_rn(v0.z, v0.w);
                    __nv_bfloat162 h2 = __floats2bfloat162_rn(v1.x, v1.y);
                    __nv_bfloat162 h3 = __floats2bfloat162_rn(v1.z, v1.w);
                    val.x = *(uint32_t*)&h0; val.y = *(uint32_t*)&h1;
                    val.z = *(uint32_t*)&h2; val.w = *(uint32_t*)&h3;
                } else {
                    float v[8];
#pragma unroll
                    for (int e = 0; e < 8; e++) {
                        int gc = gc0 + e;
                        v[e] = (gr < M && gc < K) ? Af[(size_t)gr * lda + gc] : 0.f;
                    }
                    __nv_bfloat162 h0 = __floats2bfloat162_rn(v[0], v[1]);
                    __nv_bfloat162 h1 = __floats2bfloat162_rn(v[2], v[3]);
                    __nv_bfloat162 h2 = __floats2bfloat162_rn(v[4], v[5]);
                    __nv_bfloat162 h3 = __floats2bfloat162_rn(v[6], v[7]);
                    val.x = *(uint32_t*)&h0; val.y = *(uint32_t*)&h1;
                    val.z = *(uint32_t*)&h2; val.w = *(uint32_t*)&h3;
                }
            } else {
                const __nv_bfloat16* Ah = (const __nv_bfloat16*)Aptr;
                val = (gr < M) ? *(const uint4*)(Ah + (size_t)gr * lda + gc0)
                               : make_uint4(0, 0, 0, 0);
            }
            *(uint4*)(sA + r * STR + g * 8) = val;
        }
#pragma unroll 2
        for (int idx = tid; idx < BN * 4; idx += THREADS) {
            int n = idx >> 2, g = idx & 3;
            uint4 val = *(const uint4*)(Wt + (size_t)n * ldw + k0 + g * 8);
            *(uint4*)(sB + n * STR + g * 8) = val;
        }
        __syncthreads();

        // ---- compute: 2 k-steps of 16 ----
#pragma unroll
        for (int s = 0; s < 2; s++) {
            uint32_t bfr[NATOMS][2];
#pragma unroll
            for (int j = 0; j < NATOMS; j++)
                LDMX2(bfr[j][0], bfr[j][1], bAddr[j] + s * 32);
#pragma unroll
            for (int i = 0; i < 2; i++) {
                uint32_t afr[4];
                LDMX4(afr[0], afr[1], afr[2], afr[3], aAddr[i] + s * 32);
#pragma unroll
                for (int j = 0; j < NATOMS; j++) MMA16816(acc[i][j], afr, bfr[j]);
            }
        }
        __syncthreads();
    }

    // ---- epilogue: bias + act + bf16 store ----
    const int qrow = lane >> 2, qcol = (lane & 3) * 2;
#pragma unroll
    for (int i = 0; i < 2; i++) {
#pragma unroll
        for (int j = 0; j < NATOMS; j++) {
            int gc = wn * WN + j * 8 + qcol;
            float b0 = bias[gc], b1 = bias[gc + 1];
            int gr0 = row0 + wm * 32 + i * 16 + qrow;
            float v0 = acc[i][j][0] + b0, v1 = acc[i][j][1] + b1;
            float v2 = acc[i][j][2] + b0, v3 = acc[i][j][3] + b1;
            if (act) {
                v0 = (v0 >= 0.f) ? v0 : 0.01f * v0;
                v1 = (v1 >= 0.f) ? v1 : 0.01f * v1;
                v2 = (v2 >= 0.f) ? v2 : 0.01f * v2;
                v3 = (v3 >= 0.f) ? v3 : 0.01f * v3;
            }
            if (gr0 < M) {
                __nv_bfloat162 h = __floats2bfloat162_rn(v0, v1);
                *(uint32_t*)(C + (size_t)gr0 * ldc + gc) = *(uint32_t*)&h;
            }
            if (gr0 + 8 < M) {
                __nv_bfloat162 h = __floats2bfloat162_rn(v2, v3);
                *(uint32_t*)(C + (size_t)(gr0 + 8) * ldc + gc) = *(uint32_t*)&h;
            }
        }
    }
}

// ------------------------- Aggregation (bf16, warp/segment) ----------------
// buf: [N,384] bf16; reads cols 0..127 (x), writes cols 128..383 (means).

__global__ void aggregate_kernel(__nv_bfloat16* __restrict__ buf,
                                 const int* __restrict__ rowptr,
                                 const int* __restrict__ perm, int NR) {
    int w = blockIdx.x * (blockDim.x >> 5) + (threadIdx.x >> 5);
    if (w >= NR) return;
    int lane = threadIdx.x & 31;
    int start = rowptr[w];
    int end = rowptr[w + 1];
    float a0 = 0.f, a1 = 0.f, a2 = 0.f, a3 = 0.f;
    int e = start;
    for (; e + 3 < end; e += 4) {
        int s0 = perm[e], s1 = perm[e + 1], s2 = perm[e + 2], s3 = perm[e + 3];
        uint2 v0 = *(const uint2*)(buf + (size_t)s0 * 384 + lane * 4);
        uint2 v1 = *(const uint2*)(buf + (size_t)s1 * 384 + lane * 4);
        uint2 v2 = *(const uint2*)(buf + (size_t)s2 * 384 + lane * 4);
        uint2 v3 = *(const uint2*)(buf + (size_t)s3 * 384 + lane * 4);
#define ACCUM(v)                                                              \
        {                                                                     \
            float2 f0 = __bfloat1622float2(*(__nv_bfloat162*)&(v).x);         \
            float2 f1 = __bfloat1622float2(*(__nv_bfloat162*)&(v).y);         \
            a0 += f0.x; a1 += f0.y; a2 += f1.x; a3 += f1.y;                   \
        }
        ACCUM(v0) ACCUM(v1) ACCUM(v2) ACCUM(v3)
    }
    for (; e < end; e++) {
        int s = perm[e];
        uint2 v = *(const uint2*)(buf + (size_t)s * 384 + lane * 4);
        ACCUM(v)
    }
#undef ACCUM
    int deg = end - start;
    float inv = 1.f / (float)max(deg, 1);
    __nv_bfloat162 h0 = __floats2bfloat162_rn(a0 * inv, a1 * inv);
    __nv_bfloat162 h1 = __floats2bfloat162_rn(a2 * inv, a3 * inv);
    uint2 outv;
    outv.x = *(uint32_t*)&h0;
    outv.y = *(uint32_t*)&h1;
    int node = w >> 1, r = w & 1;
    *(uint2*)(buf + (size_t)node * 384 + 128 + r * 128 + lane * 4) = outv;
}

// ------------------------- Output head -------------------------------------

__global__ void head_kernel(const __nv_bfloat16* __restrict__ buf,
                            const float* __restrict__ W_o2,
                            const float* __restrict__ b_o2,
                            float* __restrict__ out, int N) {
    int w = blockIdx.x * (blockDim.x >> 5) + (threadIdx.x >> 5);
    if (w >= N) return;
    int lane = threadIdx.x & 31;
    uint2 v = *(const uint2*)(buf + (size_t)w * 384 + lane * 4);
    float2 f0 = __bfloat1622float2(*(__nv_bfloat162*)&v.x);
    float2 f1 = __bfloat1622float2(*(__nv_bfloat162*)&v.y);
    int k = lane * 4;
    float d0 = f0.x * W_o2[(k + 0) * 2] + f0.y * W_o2[(k + 1) * 2] +
               f1.x * W_o2[(k + 2) * 2] + f1.y * W_o2[(k + 3) * 2];
    float d1 = f0.x * W_o2[(k + 0) * 2 + 1] + f0.y * W_o2[(k + 1) * 2 + 1] +
               f1.x * W_o2[(k + 2) * 2 + 1] + f1.y * W_o2[(k + 3) * 2 + 1];
#pragma unroll
    for (int off = 16; off; off >>= 1) {
        d0 += __shfl_xor_sync(0xFFFFFFFFu, d0, off);
        d1 += __shfl_xor_sync(0xFFFFFFFFu, d1, off);
    }
    if (lane == 0) {
        float l0 = d0 + b_o2[0], l1 = d1 + b_o2[1];
        float m = fmaxf(l0, l1);
        float e0 = __expf(l0 - m), e1 = __expf(l1 - m);
        float inv = 1.f / (e0 + e1);
        out[(size_t)w * 2] = e0 * inv;
        out[(size_t)w * 2 + 1] = e1 * inv;
    }
}

// ------------------------- Launch ------------------------------------------

extern "C" void kernel_launch(void* const* d_in, const int* in_sizes, int n_in,
                              void* d_out, int out_size) {
    const float* des     = (const float*)d_in[0];
    const float* tweet   = (const float*)d_in[1];
    const float* prop    = (const float*)d_in[2];
    const int*   eidx    = (const int*)d_in[3];
    const int*   etype   = (const int*)d_in[4];
    const float* W_des   = (const float*)d_in[5];
    const float* b_des   = (const float*)d_in[6];
    const float* W_tweet = (const float*)d_in[7];
    const float* b_tweet = (const float*)d_in[8];
    const float* W_prop  = (const float*)d_in[9];
    const float* b_prop  = (const float*)d_in[10];
    const float* W_in    = (const float*)d_in[11];
    const float* b_in    = (const float*)d_in[12];
    const float* W_rel   = (const float*)d_in[13];
    const float* W_root  = (const float*)d_in[14];
    const float* b_rgcn  = (const float*)d_in[15];
    const float* W_o1    = (const float*)d_in[16];
    const float* b_o1    = (const float*)d_in[17];
    const float* W_o2    = (const float*)d_in[18];
    const float* b_o2    = (const float*)d_in[19];

    const int N = in_sizes[0] / 768;
    const int E = in_sizes[4];
    const int NR = N * 2;
    const int* src = eidx;
    const int* dst = eidx + E;

    __nv_bfloat16 *A, *B, *Wt_des, *Wt_tweet, *Wt_prop, *Wt_in, *Wt_cat, *Wt_o1;
    cudaGetSymbolAddress((void**)&A, g_A);
    cudaGetSymbolAddress((void**)&B, g_B);
    cudaGetSymbolAddress((void**)&Wt_des, g_Wt_des);
    cudaGetSymbolAddress((void**)&Wt_tweet, g_Wt_tweet);
    cudaGetSymbolAddress((void**)&Wt_prop, g_Wt_prop);
    cudaGetSymbolAddress((void**)&Wt_in, g_Wt_in);
    cudaGetSymbolAddress((void**)&Wt_cat, g_Wt_cat);
    cudaGetSymbolAddress((void**)&Wt_o1, g_Wt_o1);
    int *perm, *rowptr, *cnt, *cursor, *scanb, *bsums;
    cudaGetSymbolAddress((void**)&perm, g_perm);
    cudaGetSymbolAddress((void**)&rowptr, g_rowptr);
    cudaGetSymbolAddress((void**)&cnt, g_cnt);
    cudaGetSymbolAddress((void**)&cursor, g_cursor);
    cudaGetSymbolAddress((void**)&scanb, g_scan);
    cudaGetSymbolAddress((void**)&bsums, g_bsums);

    // ---- weight prep ----
    transpose_convert<<<(32 * 768 + 255) / 256, 256>>>(W_des, Wt_des, 768, 32, 768);
    transpose_convert<<<(32 * 768 + 255) / 256, 256>>>(W_tweet, Wt_tweet, 768, 32, 768);
    transpose_convert<<<(32 * 64 + 255) / 256, 256>>>(W_prop, Wt_prop, 14, 32, 64);
    transpose_convert<<<(128 * 128 + 255) / 256, 256>>>(W_in, Wt_in, 96, 128, 128);
    transpose_convert<<<(128 * 128 + 255) / 256, 256>>>(W_o1, Wt_o1, 128, 128, 128);
    wcat_transpose<<<(128 * 384 + 255) / 256, 256>>>(W_root, W_rel, Wt_cat);

    // ---- CSR build (shared by both layers) ----
    cudaMemsetAsync(cnt, 0, (size_t)NR * sizeof(int));
    cudaMemsetAsync(cursor, 0, (size_t)NR * sizeof(int));
    count_kernel<<<(E + 255) / 256, 256>>>(dst, etype, E, cnt);
    int nb = (NR + 1023) / 1024;
    scan_block_kernel<<<nb, 1024>>>(cnt, scanb, bsums, NR);
    scan_bsums_kernel<<<1, 32>>>(bsums, nb);
    scan_finalize_kernel<<<(NR + 255) / 256, 256>>>(scanb, bsums, rowptr, NR);
    place_kernel<<<(E + 255) / 256, 256>>>(src, dst, etype, E, rowptr, cursor, perm);

    const int gm = (N + 127) / 128;

    // ---- encoder: des|tweet|prop -> B cols 0..95 ----
    gemm_mma<true, 32><<<gm, 128>>>(des, 768, Wt_des, 768, b_des, B + 0, 384, N, 768, 1);
    gemm_mma<true, 32><<<gm, 128>>>(tweet, 768, Wt_tweet, 768, b_tweet, B + 32, 384, N, 768, 1);
    gemm_mma<true, 32><<<gm, 128>>>(prop, 14, Wt_prop, 64, b_prop, B + 64, 384, N, 14, 1);
    // cat96 @ W_in -> A cols 0..127
    gemm_mma<false, 128><<<gm, 256>>>(B, 384, Wt_in, 128, b_in, A, 384, N, 96, 1);

    // ---- RGCN layer 1 ----
    aggregate_kernel<<<(NR + 7) / 8, 256>>>(A, rowptr, perm, NR);
    gemm_mma<false, 128><<<gm, 256>>>(A, 384, Wt_cat, 384, b_rgcn, B, 384, N, 384, 0);

    // ---- RGCN layer 2 ----
    aggregate_kernel<<<(NR + 7) / 8, 256>>>(B, rowptr, perm, NR);
    gemm_mma<false, 128><<<gm, 256>>>(B, 384, Wt_cat, 384, b_rgcn, A, 384, N, 384, 0);

    // ---- head ----
    gemm_mma<false, 128><<<gm, 256>>>(A, 384, Wt_o1, 128, b_o1, B, 384, N, 128, 1);
    head_kernel<<<(N + 7) / 8, 256>>>(B, W_o2, b_o2, (float*)d_out, N);
}